// round 5
// baseline (speedup 1.0000x reference)
#include <cuda_runtime.h>
#include <cstdint>

#define M_SLOTS 10
#define HW      7744          // 88*88
#define HW4     1936          // HW in float4 units
#define ROWS    8192          // B*C
#define NCH     4
#define KC4     484           // chunk length in float4 units (1936/4)
#define RPW     2             // rows per warp
#define RPB     16            // rows per block (8 warps x 2)
#define NT      256

typedef unsigned long long u64;

// Partial scores scratch: [row][chunk][m]  (1.31 MB; every slot written each launch)
__device__ float g_part[ROWS][NCH][M_SLOTS];

__device__ __forceinline__ u64 fma2(u64 a, u64 b, u64 c) {
    u64 d;
    asm("fma.rn.f32x2 %0, %1, %2, %3;" : "=l"(d) : "l"(a), "l"(b), "l"(c));
    return d;
}

__device__ __forceinline__ u64 pack2(float lo, float hi) {
    u64 t;
    asm("mov.b64 %0, {%1, %2};" : "=l"(t) : "f"(lo), "f"(hi));
    return t;
}

__device__ __forceinline__ float hsum2(u64 a) {
    float x, y;
    asm("mov.b64 {%0, %1}, %2;" : "=f"(x), "=f"(y) : "l"(a));
    return x + y;
}

struct U2 { u64 x, y; };   // one float4 as two packed f32x2 lanes

__device__ __forceinline__ U2 f4_to_u2(float4 v) {
    U2 r; r.x = pack2(v.x, v.y); r.y = pack2(v.z, v.w); return r;
}

// streaming (evict-first) float4 load: keeps L1 for the mem chunk
__device__ __forceinline__ U2 ldcs4(const float4* p) { return f4_to_u2(__ldcs(p)); }
// cached load for mem
__device__ __forceinline__ U2 ldg4(const float4* p)  { return f4_to_u2(__ldg(p)); }

// ---------------------------------------------------------------------------
// K1: partial scores.  grid = (ROWS/RPB, NCH) = 2048 blocks.  Each warp owns
// 2 rows; lanes stride the chunk's 484 float4s with a 1-deep prefetch
// pipeline.  Packed f32x2 accumulators (40 regs).  No __syncthreads.
// ---------------------------------------------------------------------------
__global__ __launch_bounds__(NT)
void k1_scores(const float* __restrict__ x, const float* __restrict__ mem) {
    const int lane = threadIdx.x & 31;
    const int warp = threadIdx.x >> 5;
    const int row0 = blockIdx.x * RPB + warp * RPW;
    const int base4 = blockIdx.y * KC4;

    const float4* __restrict__ m4  = (const float4*)mem + base4;
    const float4* __restrict__ xr0 = (const float4*)(x + (size_t)(row0 + 0) * HW) + base4;
    const float4* __restrict__ xr1 = (const float4*)(x + (size_t)(row0 + 1) * HW) + base4;

    u64 acc[RPW][M_SLOTS];
    #pragma unroll
    for (int r = 0; r < RPW; r++)
        #pragma unroll
        for (int m = 0; m < M_SLOTS; m++) acc[r][m] = 0ull;

    int j = lane;
    U2 xa0, xa1;
    if (j < KC4) { xa0 = ldcs4(xr0 + j); xa1 = ldcs4(xr1 + j); }
    while (j < KC4) {
        const int jn = j + 32;
        U2 xb0, xb1;
        if (jn < KC4) { xb0 = ldcs4(xr0 + jn); xb1 = ldcs4(xr1 + jn); }
        #pragma unroll
        for (int m = 0; m < M_SLOTS; m++) {
            U2 w = ldg4(&m4[(size_t)m * HW4 + j]);
            acc[0][m] = fma2(xa0.x, w.x, acc[0][m]);
            acc[1][m] = fma2(xa1.x, w.x, acc[1][m]);
            acc[0][m] = fma2(xa0.y, w.y, acc[0][m]);
            acc[1][m] = fma2(xa1.y, w.y, acc[1][m]);
        }
        xa0 = xb0; xa1 = xb1;
        j = jn;
    }

    // warp reduce; lane 0 stores the 20 partials for this warp's 2 rows
    #pragma unroll
    for (int r = 0; r < RPW; r++) {
        #pragma unroll
        for (int m = 0; m < M_SLOTS; m++) {
            float v = hsum2(acc[r][m]);
            v += __shfl_xor_sync(0xFFFFFFFFu, v, 16);
            v += __shfl_xor_sync(0xFFFFFFFFu, v, 8);
            v += __shfl_xor_sync(0xFFFFFFFFu, v, 4);
            v += __shfl_xor_sync(0xFFFFFFFFu, v, 2);
            v += __shfl_xor_sync(0xFFFFFFFFu, v, 1);
            if (lane == 0) g_part[row0 + r][blockIdx.y][m] = v;
        }
    }
}

// ---------------------------------------------------------------------------
// K3: softmax + value expansion.  Same geometry, no barriers: lanes 0..1 of
// each warp do the softmax for the warp's 2 rows (contiguous 160B reads),
// then 20 shfl broadcasts distribute p.  Packed f32x2 value accumulate.
// ---------------------------------------------------------------------------
__global__ __launch_bounds__(NT)
void k3_value(const float* __restrict__ mem, float* __restrict__ out) {
    const int lane = threadIdx.x & 31;
    const int warp = threadIdx.x >> 5;
    const int row0 = blockIdx.x * RPB + warp * RPW;
    const int base4 = blockIdx.y * KC4;

    // lanes 0..1: softmax for row0+lane
    float p_loc[M_SLOTS];
    {
        const int r = (lane < RPW) ? lane : 0;    // other lanes compute unused garbage
        const float* pr = &g_part[row0 + r][0][0];  // 40 contiguous floats
        float s[M_SLOTS];
        #pragma unroll
        for (int m = 0; m < M_SLOTS; m++) s[m] = 0.0f;
        #pragma unroll
        for (int c = 0; c < NCH; c++)
            #pragma unroll
            for (int m = 0; m < M_SLOTS; m++) s[m] += pr[c * M_SLOTS + m];
        float mx = -1e30f;
        #pragma unroll
        for (int m = 0; m < M_SLOTS; m++) mx = fmaxf(mx, s[m]);
        float sum = 0.0f;
        #pragma unroll
        for (int m = 0; m < M_SLOTS; m++) { s[m] = __expf(s[m] - mx); sum += s[m]; }
        float inv = 1.0f / sum;
        #pragma unroll
        for (int m = 0; m < M_SLOTS; m++) p_loc[m] = s[m] * inv;
    }

    // broadcast p[r][m] from lane r, pre-packed for f32x2
    u64 p2[RPW][M_SLOTS];
    #pragma unroll
    for (int r = 0; r < RPW; r++)
        #pragma unroll
        for (int m = 0; m < M_SLOTS; m++) {
            float pv = __shfl_sync(0xFFFFFFFFu, p_loc[m], r);
            p2[r][m] = pack2(pv, pv);
        }

    const float4* __restrict__ m4 = (const float4*)mem + base4;
    ulonglong2* __restrict__ o0 = (ulonglong2*)(out + (size_t)(row0 + 0) * HW) + base4;
    ulonglong2* __restrict__ o1 = (ulonglong2*)(out + (size_t)(row0 + 1) * HW) + base4;

    for (int j = lane; j < KC4; j += 32) {
        u64 a0x = 0ull, a0y = 0ull, a1x = 0ull, a1y = 0ull;
        #pragma unroll
        for (int m = 0; m < M_SLOTS; m++) {
            U2 w = ldg4(&m4[(size_t)m * HW4 + j]);
            a0x = fma2(p2[0][m], w.x, a0x);
            a1x = fma2(p2[1][m], w.x, a1x);
            a0y = fma2(p2[0][m], w.y, a0y);
            a1y = fma2(p2[1][m], w.y, a1y);
        }
        ulonglong2 v0; v0.x = a0x; v0.y = a0y;
        ulonglong2 v1; v1.x = a1x; v1.y = a1y;
        o0[j] = v0;
        o1[j] = v1;
    }
}

extern "C" void kernel_launch(void* const* d_in, const int* in_sizes, int n_in,
                              void* d_out, int out_size) {
    const float* x   = (const float*)d_in[0];   // [32,256,88,88]
    const float* mem = (const float*)d_in[1];   // [10,88,88]
    float* out = (float*)d_out;

    dim3 grid(ROWS / RPB, NCH);   // 512 x 4 = 2048 blocks
    k1_scores<<<grid, NT>>>(x, mem);
    k3_value<<<grid, NT>>>(mem, out);
}

// round 7
// speedup vs baseline: 1.5164x; 1.5164x over previous
#include <cuda_runtime.h>
#include <cstdint>

#define M_SLOTS 10
#define HW      7744          // 88*88
#define HW4     1936          // HW in float4 units
#define ROWS    8192          // B*C
#define KC4     242           // chunk length in float4 units (1936/8)
#define NCH     8
#define RPB     16            // rows per block
#define NT      128           // 4 warps x 4 rows

typedef unsigned long long u64;

__device__ __forceinline__ u64 fma2(u64 a, u64 b, u64 c) {
    u64 d;
    asm("fma.rn.f32x2 %0, %1, %2, %3;" : "=l"(d) : "l"(a), "l"(b), "l"(c));
    return d;
}
__device__ __forceinline__ u64 pack2(float lo, float hi) {
    u64 t;
    asm("mov.b64 %0, {%1, %2};" : "=l"(t) : "f"(lo), "f"(hi));
    return t;
}

__global__ __launch_bounds__(NT, 4)
void memaug_fused(const float* __restrict__ x,
                  const float* __restrict__ mem,
                  float* __restrict__ out) {
    __shared__ float4 w_s[M_SLOTS][KC4];   // 38,720 B chunk of mem
    __shared__ float  p_s[RPB][M_SLOTS];

    const int tid  = threadIdx.x;
    const int lane = tid & 31;
    const int warp = tid >> 5;
    const int row0 = blockIdx.x * RPB + warp * 4;

    const float4* __restrict__ m4 = (const float4*)mem;
    const float4* __restrict__ xr0 = (const float4*)(x + (size_t)(row0 + 0) * HW);
    const float4* __restrict__ xr1 = (const float4*)(x + (size_t)(row0 + 1) * HW);
    const float4* __restrict__ xr2 = (const float4*)(x + (size_t)(row0 + 2) * HW);
    const float4* __restrict__ xr3 = (const float4*)(x + (size_t)(row0 + 3) * HW);

    // ---------------- Phase 1: scores ----------------
    float acc[4][M_SLOTS];
    #pragma unroll
    for (int r = 0; r < 4; r++)
        #pragma unroll
        for (int m = 0; m < M_SLOTS; m++) acc[r][m] = 0.0f;

    for (int c = 0; c < NCH; c++) {
        // cooperative chunk load (2420 float4s / 128 threads)
        for (int idx = tid; idx < M_SLOTS * KC4; idx += NT) {
            int m = idx / KC4;
            int j = idx - m * KC4;
            w_s[m][j] = __ldg(&m4[(size_t)m * HW4 + c * KC4 + j]);
        }
        __syncthreads();

        const int base = c * KC4;
        // 2-deep prefetch pipeline over j (j in [0,242), stride 32)
        int j = lane;
        float4 z = {0.f, 0.f, 0.f, 0.f};
        float4 a0 = z, a1 = z, a2 = z, a3 = z;
        float4 b0 = z, b1 = z, b2 = z, b3 = z;
        a0 = __ldcs(xr0 + base + j); a1 = __ldcs(xr1 + base + j);
        a2 = __ldcs(xr2 + base + j); a3 = __ldcs(xr3 + base + j);
        const int j1 = j + 32;
        if (j1 < KC4) {
            b0 = __ldcs(xr0 + base + j1); b1 = __ldcs(xr1 + base + j1);
            b2 = __ldcs(xr2 + base + j1); b3 = __ldcs(xr3 + base + j1);
        }
        while (j < KC4) {
            const int j2 = j + 64;
            float4 c0 = z, c1 = z, c2 = z, c3 = z;
            if (j2 < KC4) {
                c0 = __ldcs(xr0 + base + j2); c1 = __ldcs(xr1 + base + j2);
                c2 = __ldcs(xr2 + base + j2); c3 = __ldcs(xr3 + base + j2);
            }
            #pragma unroll
            for (int m = 0; m < M_SLOTS; m++) {
                float4 w = w_s[m][j];
                acc[0][m] = fmaf(a0.x, w.x, fmaf(a0.y, w.y, fmaf(a0.z, w.z, fmaf(a0.w, w.w, acc[0][m]))));
                acc[1][m] = fmaf(a1.x, w.x, fmaf(a1.y, w.y, fmaf(a1.z, w.z, fmaf(a1.w, w.w, acc[1][m]))));
                acc[2][m] = fmaf(a2.x, w.x, fmaf(a2.y, w.y, fmaf(a2.z, w.z, fmaf(a2.w, w.w, acc[2][m]))));
                acc[3][m] = fmaf(a3.x, w.x, fmaf(a3.y, w.y, fmaf(a3.z, w.z, fmaf(a3.w, w.w, acc[3][m]))));
            }
            a0 = b0; a1 = b1; a2 = b2; a3 = b3;
            b0 = c0; b1 = c1; b2 = c2; b3 = c3;
            j += 32;
        }
        __syncthreads();
    }

    // warp reduce -> p_s
    #pragma unroll
    for (int r = 0; r < 4; r++) {
        #pragma unroll
        for (int m = 0; m < M_SLOTS; m++) {
            float v = acc[r][m];
            v += __shfl_xor_sync(0xFFFFFFFFu, v, 16);
            v += __shfl_xor_sync(0xFFFFFFFFu, v, 8);
            v += __shfl_xor_sync(0xFFFFFFFFu, v, 4);
            v += __shfl_xor_sync(0xFFFFFFFFu, v, 2);
            v += __shfl_xor_sync(0xFFFFFFFFu, v, 1);
            if (lane == 0) p_s[warp * 4 + r][m] = v;
        }
    }
    __syncthreads();

    // softmax: one thread per row
    if (tid < RPB) {
        float s[M_SLOTS];
        float mx = -1e30f;
        #pragma unroll
        for (int m = 0; m < M_SLOTS; m++) { s[m] = p_s[tid][m]; mx = fmaxf(mx, s[m]); }
        float sum = 0.0f;
        #pragma unroll
        for (int m = 0; m < M_SLOTS; m++) { s[m] = __expf(s[m] - mx); sum += s[m]; }
        float inv = 1.0f / sum;
        #pragma unroll
        for (int m = 0; m < M_SLOTS; m++) p_s[tid][m] = s[m] * inv;
    }
    __syncthreads();

    // ---------------- Phase 2: value (f32x2) ----------------
    u64 p2[4][M_SLOTS];
    #pragma unroll
    for (int r = 0; r < 4; r++)
        #pragma unroll
        for (int m = 0; m < M_SLOTS; m++) {
            float pv = p_s[warp * 4 + r][m];
            p2[r][m] = pack2(pv, pv);
        }

    ulonglong2* __restrict__ o0 = (ulonglong2*)(out + (size_t)(row0 + 0) * HW);
    ulonglong2* __restrict__ o1 = (ulonglong2*)(out + (size_t)(row0 + 1) * HW);
    ulonglong2* __restrict__ o2 = (ulonglong2*)(out + (size_t)(row0 + 2) * HW);
    ulonglong2* __restrict__ o3 = (ulonglong2*)(out + (size_t)(row0 + 3) * HW);

    for (int c = 0; c < NCH; c++) {
        for (int idx = tid; idx < M_SLOTS * KC4; idx += NT) {
            int m = idx / KC4;
            int j = idx - m * KC4;
            w_s[m][j] = __ldg(&m4[(size_t)m * HW4 + c * KC4 + j]);
        }
        __syncthreads();

        const int base = c * KC4;
        for (int j = lane; j < KC4; j += 32) {
            u64 a0x = 0ull, a0y = 0ull, a1x = 0ull, a1y = 0ull;
            u64 a2x = 0ull, a2y = 0ull, a3x = 0ull, a3y = 0ull;
            #pragma unroll
            for (int m = 0; m < M_SLOTS; m++) {
                ulonglong2 w = *(const ulonglong2*)&w_s[m][j];
                a0x = fma2(p2[0][m], w.x, a0x);  a0y = fma2(p2[0][m], w.y, a0y);
                a1x = fma2(p2[1][m], w.x, a1x);  a1y = fma2(p2[1][m], w.y, a1y);
                a2x = fma2(p2[2][m], w.x, a2x);  a2y = fma2(p2[2][m], w.y, a2y);
                a3x = fma2(p2[3][m], w.x, a3x);  a3y = fma2(p2[3][m], w.y, a3y);
            }
            ulonglong2 v0; v0.x = a0x; v0.y = a0y; o0[base + j] = v0;
            ulonglong2 v1; v1.x = a1x; v1.y = a1y; o1[base + j] = v1;
            ulonglong2 v2; v2.x = a2x; v2.y = a2y; o2[base + j] = v2;
            ulonglong2 v3; v3.x = a3x; v3.y = a3y; o3[base + j] = v3;
        }
        __syncthreads();
    }
}

extern "C" void kernel_launch(void* const* d_in, const int* in_sizes, int n_in,
                              void* d_out, int out_size) {
    const float* x   = (const float*)d_in[0];   // [32,256,88,88]
    const float* mem = (const float*)d_in[1];   // [10,88,88]
    float* out = (float*)d_out;

    dim3 grid(ROWS / RPB);    // 512 blocks
    memaug_fused<<<grid, NT>>>(x, mem, out);
}